// round 17
// baseline (speedup 1.0000x reference)
#include <cuda_runtime.h>

#define H 1024
#define L 256
#define BATCH 64
#define NCTA 128
#define NTH 256
#define IDX_PER_CTA 8
#define TCHUNK 4               // phase-1 parallelism over t

// Scratch (no cudaMalloc allowed). Zero-initialized at module load.
__device__ uint2    g_hw[L * H];         // per-index {h_bits, tag} 8B chunks
__device__ float    g_hs[L * H];         // plain trajectory copy (for feat bcast)
__device__ float    g_gi[L * NCTA * 24]; // gi: [t][cta][gate(3)][warp(8)]
__device__ unsigned g_epoch;             // bumped once per kernel_launch
__device__ float    g_dot;               // accumulated w_out . feat_row

__device__ __forceinline__ float sigmoidf_(float v) {
    return 1.0f / (1.0f + expf(-v));
}

__device__ __forceinline__ float warp_sum(float v) {
    #pragma unroll
    for (int off = 16; off; off >>= 1)
        v += __shfl_xor_sync(0xffffffffu, v, off);
    return v;
}

// Packed dual-FMA (Blackwell f32x2) — PTX-only, ptxas never emits from C++.
__device__ __forceinline__ unsigned long long fma2(unsigned long long a,
                                                   unsigned long long b,
                                                   unsigned long long c) {
    unsigned long long d;
    asm("fma.rn.f32x2 %0, %1, %2, %3;" : "=l"(d) : "l"(a), "l"(b), "l"(c));
    return d;
}
__device__ __forceinline__ float unpack_sum(unsigned long long a) {
    float lo, hi;
    asm("mov.b64 {%0,%1}, %2;" : "=f"(lo), "=f"(hi) : "l"(a));
    return lo + hi;
}

// L2-direct 8B integer load/store; volatile so poll loops re-issue.
__device__ __forceinline__ uint2 ldcg_u2(const uint2* p) {
    uint2 v;
    asm volatile("ld.global.cg.v2.u32 {%0,%1}, [%2];"
                 : "=r"(v.x), "=r"(v.y) : "l"(p) : "memory");
    return v;
}
__device__ __forceinline__ void stcg_u2(uint2* p, uint2 v) {
    asm volatile("st.global.cg.v2.u32 [%0], {%1,%2};"
                 :: "l"(p), "r"(v.x), "r"(v.y) : "memory");
}

__global__ void init_kernel() {
    g_epoch = g_epoch + 1u;   // unique tag space per launch; no re-init of g_hw
    g_dot = 0.f;
}

__device__ __forceinline__ int detect_stride(const int* x32) {
    // int64 tokens -> odd int32 words all zero
    int odd_all_zero = 1;
    #pragma unroll
    for (int k = 0; k < 8; k++)
        if (x32[2 * k + 1] != 0) odd_all_zero = 0;
    return odd_all_zero ? 2 : 1;
}

// ===== Phase 1: gi[t] = e_t @ W_ih^T (+ folded biases); parallel over t =====
__global__ void __launch_bounds__(NTH, 2) gates_kernel(
    const int* __restrict__ x32,
    const float* __restrict__ emb,
    const float* __restrict__ w_ih,
    const float* __restrict__ b_ih,
    const float* __restrict__ b_hh)
{
    __shared__ float4 e_s4[H / 4];

    const int tid = threadIdx.x;
    const int w   = tid >> 5;
    const int l   = tid & 31;
    const int cta = blockIdx.x;
    const int j   = cta * IDX_PER_CTA + w;
    const int t0  = blockIdx.y * (L / TCHUNK);
    const int t1  = t0 + (L / TCHUNK);

    const int stride = detect_stride(x32);

    float gib0 = 0.f, gib1 = 0.f, gib2 = 0.f;
    if (l == 0) {
        gib0 = b_ih[j]         + b_hh[j];
        gib1 = b_ih[H + j]     + b_hh[H + j];
        gib2 = b_ih[2 * H + j];
    }

    ulonglong2 wr0[8], wr1[8], wr2[8];
    {
        const float* base = w_ih + (size_t)j * H + l * 4;
        #pragma unroll
        for (int k = 0; k < 8; k++) {
            wr0[k] = *(const ulonglong2*)(base + k * 128);
            wr1[k] = *(const ulonglong2*)(base + (size_t)H * H + k * 128);
            wr2[k] = *(const ulonglong2*)(base + (size_t)2 * H * H + k * 128);
        }
    }
    const ulonglong2* e_p2 = (const ulonglong2*)e_s4;

    {
        int tok0 = x32[(size_t)t0 * BATCH * stride];
        float4 cur = *(const float4*)(emb + (size_t)tok0 * H + tid * 4);
        for (int t = t0; t < t1; t++) {
            e_s4[tid] = cur;
            __syncthreads();
            float4 nxt = make_float4(0.f, 0.f, 0.f, 0.f);
            if (t + 1 < t1) {
                int tk = x32[(size_t)(t + 1) * BATCH * stride];
                nxt = *(const float4*)(emb + (size_t)tk * H + tid * 4);
            }
            unsigned long long a0 = 0, a1 = 0, a2 = 0;
            #pragma unroll
            for (int k = 0; k < 8; k++) {
                ulonglong2 ee = e_p2[k * 32 + l];
                a0 = fma2(wr0[k].x, ee.x, a0); a0 = fma2(wr0[k].y, ee.y, a0);
                a1 = fma2(wr1[k].x, ee.x, a1); a1 = fma2(wr1[k].y, ee.y, a1);
                a2 = fma2(wr2[k].x, ee.x, a2); a2 = fma2(wr2[k].y, ee.y, a2);
            }
            float s0 = warp_sum(unpack_sum(a0));
            float s1 = warp_sum(unpack_sum(a1));
            float s2 = warp_sum(unpack_sum(a2));
            if (l == 0) {
                float* gi = &g_gi[((size_t)t * NCTA + cta) * 24];
                gi[w]      = s0 + gib0;
                gi[8 + w]  = s1 + gib1;
                gi[16 + w] = s2 + gib2;
            }
            __syncthreads();
            cur = nxt;
        }
    }
}

// ===== Phase 2: recurrence; per-warp autonomous tagged publish =====
__global__ void __launch_bounds__(NTH, 1) rec_kernel(
    const float* __restrict__ w_hh,
    const float* __restrict__ b_hh,
    const float* __restrict__ w_out)
{
    __shared__ float4 h_s4[H / 4];     // assembled h_{t-1}
    __shared__ float  dotbuf[8];

    const int tid = threadIdx.x;
    const int w   = tid >> 5;
    const int l   = tid & 31;
    const int cta = blockIdx.x;
    const int j   = cta * IDX_PER_CTA + w;
    const ulonglong2* h_p2 = (const ulonglong2*)h_s4;

    const unsigned ebase = g_epoch << 8;   // init_kernel ran earlier in stream

    float bhn = 0.f;
    if (l == 0) bhn = b_hh[2 * H + j];

    ulonglong2 wr0[8], wr1[8], wr2[8];
    {
        const float* base = w_hh + (size_t)j * H + l * 4;
        #pragma unroll
        for (int k = 0; k < 8; k++) {
            wr0[k] = *(const ulonglong2*)(base + k * 128);
            wr1[k] = *(const ulonglong2*)(base + (size_t)H * H + k * 128);
            wr2[k] = *(const ulonglong2*)(base + (size_t)2 * H * H + k * 128);
        }
    }

    float dot_local = 0.f;
    float h_prev = 0.f;    // lane0: own h_{t-1}[j], carried in-register

    for (int t = 0; t < L; t++) {
        // off-chain prefetches (h-independent)
        float gi0 = 0.f, gi1 = 0.f, gi2 = 0.f, wo = 0.f;
        if (l == 0) {
            const float* gi = &g_gi[((size_t)t * NCTA + cta) * 24];
            gi0 = __ldcg(gi + w);
            gi1 = __ldcg(gi + 8 + w);
            gi2 = __ldcg(gi + 16 + w);
            wo  = __ldg(&w_out[(size_t)t * H + j]);
        }

        if (t == 0) {
            h_s4[tid] = make_float4(0.f, 0.f, 0.f, 0.f);
        } else {
            // Poll 4 chunks: data+tag in one 8B load each. Poll-success implies
            // ALL warps everywhere (incl. own CTA) published step t-1, i.e.
            // finished reading h_s — so overwriting h_s here is safe (no bar#2).
            const unsigned etag = ebase | (unsigned)(t - 1);
            const uint2* pb = g_hw + (size_t)(t - 1) * H + 4 * tid;
            uint2 c0, c1, c2, c3;
            bool o0 = false, o1 = false, o2 = false, o3 = false;
            int spins = 0;
            for (;;) {
                if (!o0) { c0 = ldcg_u2(pb + 0); o0 = (c0.y == etag); }
                if (!o1) { c1 = ldcg_u2(pb + 1); o1 = (c1.y == etag); }
                if (!o2) { c2 = ldcg_u2(pb + 2); o2 = (c2.y == etag); }
                if (!o3) { c3 = ldcg_u2(pb + 3); o3 = (c3.y == etag); }
                if (o0 && o1 && o2 && o3) break;
                if (++spins > 8192) __nanosleep(32);
                if (spins > (1 << 20)) break;    // escape: fail visibly, not hang
            }
            h_s4[tid] = make_float4(__uint_as_float(c0.x), __uint_as_float(c1.x),
                                    __uint_as_float(c2.x), __uint_as_float(c3.x));
        }
        __syncthreads();   // bar#1: h_s assembled and visible CTA-wide

        unsigned long long a0 = 0, a1 = 0, a2 = 0;
        #pragma unroll
        for (int k = 0; k < 8; k++) {
            ulonglong2 hh = h_p2[k * 32 + l];
            a0 = fma2(wr0[k].x, hh.x, a0); a0 = fma2(wr0[k].y, hh.y, a0);
            a1 = fma2(wr1[k].x, hh.x, a1); a1 = fma2(wr1[k].y, hh.y, a1);
            a2 = fma2(wr2[k].x, hh.x, a2); a2 = fma2(wr2[k].y, hh.y, a2);
        }
        float s0 = warp_sum(unpack_sum(a0));
        float s1 = warp_sum(unpack_sum(a1));
        float s2 = warp_sum(unpack_sum(a2));

        if (l == 0) {
            float r  = sigmoidf_(gi0 + s0);
            float z  = sigmoidf_(gi1 + s1);
            float n  = tanhf(gi2 + r * (s2 + bhn));
            float h2 = z * (h_prev - n) + n;
            h_prev = h2;
            // publish the instant this warp's gates finish — no barrier, no funnel
            uint2 c; c.x = __float_as_uint(h2); c.y = ebase | (unsigned)t;
            stcg_u2(g_hw + (size_t)t * H + j, c);
            g_hs[(size_t)t * H + j] = h2;          // off-chain copy for bcast
            dot_local = fmaf(wo, h2, dot_local);   // off-chain bookkeeping
        }
        // NOTE: no bar#2 — next iteration's poll provides the read-completion guard
    }

    // one atomic per CTA for the output dot
    if (l == 0) dotbuf[w] = dot_local;
    __syncthreads();
    if (tid == 0) {
        float s = 0.f;
        #pragma unroll
        for (int k = 0; k < 8; k++) s += dotbuf[k];
        atomicAdd(&g_dot, s);
    }
}

// feat[b, :] = g_hs (64 identical rows) — pure bandwidth.
__global__ void feat_bcast_kernel(float* __restrict__ out) {
    size_t i = (size_t)blockIdx.x * blockDim.x + threadIdx.x;
    const float4* src = (const float4*)g_hs;
    ((float4*)out)[i] = src[i & (size_t)(L * H / 4 - 1)];
}

__global__ void finalize_kernel(const float* __restrict__ b_out,
                                float* __restrict__ out) {
    float v = 1.0f / (1.0f + expf(-(g_dot + b_out[0])));
    if (threadIdx.x < BATCH) out[threadIdx.x] = v;
}

extern "C" void kernel_launch(void* const* d_in, const int* in_sizes, int n_in,
                              void* d_out, int out_size) {
    const int*   x     = (const int*)d_in[0];
    const float* emb   = (const float*)d_in[1];
    const float* w_ih  = (const float*)d_in[2];
    const float* w_hh  = (const float*)d_in[3];
    const float* b_ih  = (const float*)d_in[4];
    const float* b_hh  = (const float*)d_in[5];
    const float* w_out = (const float*)d_in[6];
    const float* b_out = (const float*)d_in[7];
    float* out = (float*)d_out;
    (void)in_sizes; (void)n_in;

    init_kernel<<<1, 1>>>();
    dim3 ggrid(NCTA, TCHUNK);
    gates_kernel<<<ggrid, NTH>>>(x, emb, w_ih, b_ih, b_hh);
    rec_kernel<<<NCTA, NTH>>>(w_hh, b_hh, w_out);

    const size_t BLH = (size_t)BATCH * L * H;   // 16,777,216
    if ((size_t)out_size >= BLH) {
        feat_bcast_kernel<<<(unsigned)(BLH / 4 / 256), 256>>>(out);
        if ((size_t)out_size >= BLH + BATCH)
            finalize_kernel<<<1, 64>>>(b_out, out + BLH);
    } else {
        finalize_kernel<<<1, 64>>>(b_out, out);
    }
}